// round 12
// baseline (speedup 1.0000x reference)
#include <cuda_runtime.h>
#include <cuda_fp16.h>
#include <cstdint>

// ---------------------------------------------------------------------------
// MoE, sm_103: fp16 mma.sync (m16n8k16, fp32 accum) + warp specialization.
//   out[t,o] = sum_e softmax_e(x@Wg+bg)_e * gelu(x@We[e] + be[e])
// B*T=16384, D=256, O=256, E=16.
//
// moe_kernel: CTA = 128 tokens x 128 cols (1 CTA/SM), all 16 experts.
//   18 warps: 16 compute (4Mx4N, warp tile 32x32), 2 producer.
//   Ring = 2 x 64KB (one full expert each), one mbarrier wait per expert.
//   Epilogue: f32x2-PACKED branchless A&S-erf GELU (Blackwell FFMA2).
// ---------------------------------------------------------------------------

#define NTOK   16384
#define DD     256
#define OO     256
#define EE     16
#define TILE_M 128
#define TILE_N 128
#define NTHREADS 576          // 16 compute warps + 2 producer warps
#define NBUF   2              // expert-granular double buffer

// smem layout (bytes)
#define SM_A      0                      // fp16 A: [wm4][kc8][ks2][mi2][lane32][16B]
#define SM_A_SIZE 65536
#define SM_B      65536                  // 2 x 64KB expert buffers
#define SM_B_BUF  65536
#define SM_BAR    (SM_B + NBUF * SM_B_BUF)   // = 196608
#define MB_FULL(i)  (SM_BAR + (i) * 8)
#define MB_EMPTY(i) (SM_BAR + 16 + (i) * 8)
#define SMEM_TOTAL  (SM_BAR + 64)        // 196672 B -> 1 CTA/SM

// scratch: We as fp16 in m16n8k16 fragment order.
__device__ uint4 g_WeBh[EE * DD * OO / 8];   // 2 MB
__device__ float g_gate[NTOK * EE];

typedef unsigned long long u64;

// ---------------------------------------------------------------------------
__device__ __forceinline__ uint32_t pack_h2(float lo, float hi) {
    __half2 h = __floats2half2_rn(lo, hi);
    return *reinterpret_cast<uint32_t*>(&h);
}
__device__ __forceinline__ uint32_t smem_u32(const void* p) {
    uint32_t a;
    asm("{ .reg .u64 t; cvta.to.shared.u64 t, %1; cvt.u32.u64 %0, t; }"
        : "=r"(a) : "l"(p));
    return a;
}
__device__ __forceinline__ void mma_f16(float* c, const uint4& a,
                                        uint32_t b0, uint32_t b1) {
    asm volatile(
        "mma.sync.aligned.m16n8k16.row.col.f32.f16.f16.f32 "
        "{%0,%1,%2,%3}, {%4,%5,%6,%7}, {%8,%9}, {%0,%1,%2,%3};\n"
        : "+f"(c[0]), "+f"(c[1]), "+f"(c[2]), "+f"(c[3])
        : "r"(a.x), "r"(a.y), "r"(a.z), "r"(a.w), "r"(b0), "r"(b1));
}
__device__ __forceinline__ void cp_async16(uint32_t saddr, const void* gaddr) {
    asm volatile("cp.async.cg.shared.global [%0], [%1], 16;\n"
                 :: "r"(saddr), "l"(gaddr));
}

// ---- packed f32x2 helpers (Blackwell FFMA2/FMUL2/FADD2 via PTX) ----------
__device__ __forceinline__ u64 pk2(float a, float b) {
    u64 r; asm("mov.b64 %0,{%1,%2};" : "=l"(r) : "f"(a), "f"(b)); return r;
}
__device__ __forceinline__ float2 upk2(u64 v) {
    float2 r; asm("mov.b64 {%0,%1},%2;" : "=f"(r.x), "=f"(r.y) : "l"(v)); return r;
}
__device__ __forceinline__ u64 fma2_(u64 a, u64 b, u64 c) {
    u64 d; asm("fma.rn.f32x2 %0,%1,%2,%3;" : "=l"(d) : "l"(a), "l"(b), "l"(c));
    return d;
}
__device__ __forceinline__ u64 mul2_(u64 a, u64 b) {
    u64 d; asm("mul.rn.f32x2 %0,%1,%2;" : "=l"(d) : "l"(a), "l"(b)); return d;
}
__device__ __forceinline__ u64 add2_(u64 a, u64 b) {
    u64 d; asm("add.rn.f32x2 %0,%1,%2;" : "=l"(d) : "l"(a), "l"(b)); return d;
}
__device__ __forceinline__ u64 dup(float c) {
    uint32_t u = __float_as_uint(c);
    return ((u64)u << 32) | u;
}
__device__ __forceinline__ float rcp_(float x) {
    float r; asm("rcp.approx.f32 %0,%1;" : "=f"(r) : "f"(x)); return r;
}
__device__ __forceinline__ float ex2_(float x) {
    float r; asm("ex2.approx.f32 %0,%1;" : "=f"(r) : "f"(x)); return r;
}

// packed GELU on (v0,v1): 0.5v(1+erf(v/sqrt2)), erf via A&S 7.1.26
// (|err|<=1.5e-7). All FMA work on the 2-lane f32x2 pipe; 2 MUFU per lane.
__device__ __forceinline__ u64 gelu2(u64 V) {
    const u64 ABSM = 0x7FFFFFFF7FFFFFFFull, SGNM = 0x8000000080000000ull;
    u64 AZ = mul2_(V & ABSM, dup(0.70710678118654752f));   // z = |v|/sqrt2
    u64 T  = fma2_(dup(0.3275911f), AZ, dup(1.0f));
    float2 t = upk2(T);
    u64 Tt = pk2(rcp_(t.x), rcp_(t.y));
    u64 P = fma2_(Tt, dup(1.061405429f), dup(-1.453152027f));
    P = fma2_(Tt, P, dup(1.421413741f));
    P = fma2_(Tt, P, dup(-0.284496736f));
    P = fma2_(Tt, P, dup(0.254829592f));
    P = mul2_(P, Tt);
    u64 W = mul2_(AZ, AZ);
    W = mul2_(W, dup(-1.44269504088896f));                 // -z^2*log2(e)
    float2 w = upk2(W);
    u64 E = pk2(ex2_(w.x), ex2_(w.y));
    u64 ER = fma2_(P ^ SGNM, E, dup(1.0f));                // erf(z), z>=0
    ER = ER | (V & SGNM);                                  // copysign
    u64 HV = mul2_(V, dup(0.5f));
    return fma2_(HV, ER, HV);
}

#define MBAR_INIT(a, n) \
    asm volatile("mbarrier.init.shared.b64 [%0], %1;" :: "r"(a), "r"((uint32_t)(n)) : "memory")
#define MBAR_ARRIVE(a) \
    asm volatile("mbarrier.arrive.shared.b64 _, [%0];" :: "r"(a) : "memory")
#define MBAR_WAIT(a, ph) do {                                                 \
    asm volatile("{\n\t.reg .pred P1;\n\t"                                    \
        "WL_%=:\n\tmbarrier.try_wait.parity.acquire.cta.shared::cta.b64 P1, [%0], %1, 0x989680;\n\t" \
        "@P1 bra.uni WD_%=;\n\tbra.uni WL_%=;\n\tWD_%=:\n\t}"                 \
        :: "r"(a), "r"((uint32_t)(ph)) : "memory");                           \
} while (0)
#define CP_ARRIVE_NOINC(a) \
    asm volatile("cp.async.mbarrier.arrive.noinc.shared::cta.b64 [%0];" :: "r"(a) : "memory")
#define NAMED_BAR(id, n) \
    asm volatile("bar.sync %0, %1;" :: "r"(id), "r"(n) : "memory")

// ---------------------------------------------------------------------------
// Pre-pass: We[e][d][o] -> fp16 m16n8k16 fragment order (unchanged).
// ---------------------------------------------------------------------------
__global__ void permute_we(const float* __restrict__ We) {
    int idx = blockIdx.x * blockDim.x + threadIdx.x;   // 0 .. 131071
    int lane = idx & 31;
    int jp   = (idx >> 5) & 1;
    int ks   = (idx >> 6) & 1;
    int wn   = (idx >> 7) & 3;
    int kc   = (idx >> 9) & 7;
    int ct   = (idx >> 12) & 1;
    int e    = idx >> 13;
    int g = lane >> 2, t = lane & 3;
    int k0 = kc * 32 + ks * 16 + 2 * t;
    int nA = ct * 128 + wn * 32 + jp * 16 + g;
    const float* w = We + (size_t)e * DD * OO;
    uint4 v;
    v.x = pack_h2(w[(size_t)k0 * OO + nA],       w[(size_t)(k0 + 1) * OO + nA]);
    v.y = pack_h2(w[(size_t)(k0 + 8) * OO + nA], w[(size_t)(k0 + 9) * OO + nA]);
    v.z = pack_h2(w[(size_t)k0 * OO + nA + 8],       w[(size_t)(k0 + 1) * OO + nA + 8]);
    v.w = pack_h2(w[(size_t)(k0 + 8) * OO + nA + 8], w[(size_t)(k0 + 9) * OO + nA + 8]);
    g_WeBh[idx] = v;
}

// ---------------------------------------------------------------------------
// Main kernel: 1 CTA/SM, 128x128 tile.
// ---------------------------------------------------------------------------
__global__ __launch_bounds__(NTHREADS, 1)
void moe_kernel(const float* __restrict__ x, const float* __restrict__ be,
                const float* __restrict__ Wg, const float* __restrict__ bg,
                float* __restrict__ out) {
    extern __shared__ float smf[];
    char* smc = reinterpret_cast<char*>(smf);
    const uint32_t sbase = smem_u32(smc);
    const int tid  = threadIdx.x;
    const int wid  = tid >> 5;
    const int lane = tid & 31;
    const int token0 = (blockIdx.x >> 1) * TILE_M;
    const int ct     = blockIdx.x & 1;
    const int col0   = ct * TILE_N;

    if (tid == 0) {
        #pragma unroll
        for (int i = 0; i < NBUF; i++) {
            MBAR_INIT(sbase + MB_FULL(i), 64);   // 64 producer threads, noinc
            MBAR_INIT(sbase + MB_EMPTY(i), 16);  // one arrive per compute warp
        }
    }
    __syncthreads();

    if (wid >= 16) {
        // ========== producer warps: one full expert (64KB) per commit ======
        const int ltid = tid - 512;              // 0..63
        int ph_e[NBUF] = {0, 0};
        #pragma unroll 1
        for (int e = 0; e < EE; e++) {
            const int buf = e & 1;
            if (e >= NBUF) {
                MBAR_WAIT(sbase + MB_EMPTY(buf), ph_e[buf]);
                ph_e[buf] ^= 1;
            }
            const char* gsrc = reinterpret_cast<const char*>(g_WeBh)
                             + (size_t)(e * 2 + ct) * 65536 + ltid * 16;
            const uint32_t dst = sbase + SM_B + (uint32_t)buf * SM_B_BUF
                               + (uint32_t)ltid * 16;
            #pragma unroll
            for (int i = 0; i < 64; i++)
                cp_async16(dst + i * 1024, gsrc + i * 1024);
            CP_ARRIVE_NOINC(sbase + MB_FULL(buf));
        }
    } else {
        // ================= compute warps (16 x 32 threads) =================
        const int wm = wid & 3;          // 4 row groups of 32 tokens
        const int wn = wid >> 2;         // 4 col groups of 32 cols

        // ---- build A (fp16 fragment order): 4096 16B slots --------------
        {
            #pragma unroll
            for (int it = 0; it < 8; it++) {
                int idx = tid + (it << 9);         // tid 0..511
                int ln = idx & 31;
                int mi = (idx >> 5) & 1;
                int ks = (idx >> 6) & 1;
                int kc = (idx >> 7) & 7;
                int wmm = idx >> 10;               // 0..3
                int g = ln >> 2, t = ln & 3;
                int r0 = token0 + wmm * 32 + mi * 16 + g;
                int c0 = kc * 32 + ks * 16 + 2 * t;
                const float* xp = x + (size_t)r0 * DD + c0;
                float2 p00 = *reinterpret_cast<const float2*>(xp);
                float2 p10 = *reinterpret_cast<const float2*>(xp + 8 * DD);
                float2 p01 = *reinterpret_cast<const float2*>(xp + 8);
                float2 p11 = *reinterpret_cast<const float2*>(xp + 8 * DD + 8);
                uint4 v;
                v.x = pack_h2(p00.x, p00.y);
                v.y = pack_h2(p10.x, p10.y);
                v.z = pack_h2(p01.x, p01.y);
                v.w = pack_h2(p11.x, p11.y);
                *reinterpret_cast<uint4*>(smc + SM_A + (size_t)idx * 16) = v;
            }
        }
        // ---- gate: softmax(x@Wg+bg). 4 threads/token, 4 experts each ----
        {
            const int tok = tid >> 2;          // 0..127
            const int q   = tid & 3;
            float acc0 = 0.f, acc1 = 0.f, acc2 = 0.f, acc3 = 0.f;
            const float4* x4 = reinterpret_cast<const float4*>(
                x + (size_t)(token0 + tok) * DD);
            const float4* wg4 = reinterpret_cast<const float4*>(Wg);
            #pragma unroll 4
            for (int d4 = 0; d4 < 64; d4++) {
                float4 xv = x4[d4];
                float4 w0 = wg4[(d4 * 4 + 0) * 4 + q];
                float4 w1 = wg4[(d4 * 4 + 1) * 4 + q];
                float4 w2 = wg4[(d4 * 4 + 2) * 4 + q];
                float4 w3 = wg4[(d4 * 4 + 3) * 4 + q];
                acc0 += xv.x * w0.x + xv.y * w1.x + xv.z * w2.x + xv.w * w3.x;
                acc1 += xv.x * w0.y + xv.y * w1.y + xv.z * w2.y + xv.w * w3.y;
                acc2 += xv.x * w0.z + xv.y * w1.z + xv.z * w2.z + xv.w * w3.z;
                acc3 += xv.x * w0.w + xv.y * w1.w + xv.z * w2.w + xv.w * w3.w;
            }
            acc0 += __ldg(bg + q * 4 + 0);
            acc1 += __ldg(bg + q * 4 + 1);
            acc2 += __ldg(bg + q * 4 + 2);
            acc3 += __ldg(bg + q * 4 + 3);
            float m = fmaxf(fmaxf(acc0, acc1), fmaxf(acc2, acc3));
            m = fmaxf(m, __shfl_xor_sync(0xFFFFFFFFu, m, 1));
            m = fmaxf(m, __shfl_xor_sync(0xFFFFFFFFu, m, 2));
            float v0 = __expf(acc0 - m), v1 = __expf(acc1 - m);
            float v2 = __expf(acc2 - m), v3 = __expf(acc3 - m);
            float s = v0 + v1 + v2 + v3;
            s += __shfl_xor_sync(0xFFFFFFFFu, s, 1);
            s += __shfl_xor_sync(0xFFFFFFFFu, s, 2);
            float inv = 1.0f / s;
            float4 g = make_float4(v0 * inv, v1 * inv, v2 * inv, v3 * inv);
            *reinterpret_cast<float4*>(
                g_gate + (size_t)(token0 + tok) * EE + q * 4) = g;
        }
        NAMED_BAR(1, 512);     // compute warps only: A + gate ready

        // packed output accumulators: [mi][j][pair]  (pair0 = row r, pair1 = row r+8)
        u64 oacc2[2][4][2];
        #pragma unroll
        for (int mi = 0; mi < 2; mi++)
            #pragma unroll
            for (int j = 0; j < 4; j++) {
                oacc2[mi][j][0] = 0ull;
                oacc2[mi][j][1] = 0ull;
            }

        int ph_f[NBUF] = {0, 0};

        #pragma unroll 1
        for (int e = 0; e < EE; e++) {
            const int buf = e & 1;
            MBAR_WAIT(sbase + MB_FULL(buf), ph_f[buf]);
            ph_f[buf] ^= 1;

            float hacc[2][4][4];
            #pragma unroll
            for (int mi = 0; mi < 2; mi++)
                #pragma unroll
                for (int j = 0; j < 4; j++)
                    #pragma unroll
                    for (int q = 0; q < 4; q++) hacc[mi][j][q] = 0.0f;

            const char* bbuf = smc + SM_B + buf * SM_B_BUF;
            const char* abase = smc + SM_A + wm * 16384 + lane * 16;

            // wait-free inner loop: 8 chunks of pure LDS+MMA
            #pragma unroll 2
            for (int kc = 0; kc < 8; kc++) {
                const char* ab = abase + kc * 2048;
                const char* bp0 = bbuf + kc * 8192 + wn * 2048 + lane * 16;
                #pragma unroll
                for (int ks = 0; ks < 2; ks++) {
                    uint4 A0 = *reinterpret_cast<const uint4*>(ab + ks * 1024);
                    uint4 A1 = *reinterpret_cast<const uint4*>(ab + ks * 1024 + 512);
                    const char* bp = bp0 + ks * 1024;
                    uint4 B0 = *reinterpret_cast<const uint4*>(bp);
                    uint4 B1 = *reinterpret_cast<const uint4*>(bp + 512);
                    mma_f16(hacc[0][0], A0, B0.x, B0.y);
                    mma_f16(hacc[1][0], A1, B0.x, B0.y);
                    mma_f16(hacc[0][1], A0, B0.z, B0.w);
                    mma_f16(hacc[1][1], A1, B0.z, B0.w);
                    mma_f16(hacc[0][2], A0, B1.x, B1.y);
                    mma_f16(hacc[1][2], A1, B1.x, B1.y);
                    mma_f16(hacc[0][3], A0, B1.z, B1.w);
                    mma_f16(hacc[1][3], A1, B1.z, B1.w);
                }
            }
            if (lane == 0) MBAR_ARRIVE(sbase + MB_EMPTY(buf));

            // ---- epilogue: packed bias + gelu + gate-weighted accumulate --
            #pragma unroll
            for (int mi = 0; mi < 2; mi++) {
                int rr = token0 + wm * 32 + mi * 16 + (lane >> 2);
                u64 G0 = dup(__ldg(g_gate + (size_t)rr * EE + e));
                u64 G1 = dup(__ldg(g_gate + (size_t)(rr + 8) * EE + e));
                #pragma unroll
                for (int j = 0; j < 4; j++) {
                    int n0 = col0 + wn * 32 + j * 8 + (lane & 3) * 2;
                    float2 bv = __ldg(reinterpret_cast<const float2*>(
                        be + (size_t)e * OO + n0));
                    u64 BV = pk2(bv.x, bv.y);
                    u64 H01 = add2_(pk2(hacc[mi][j][0], hacc[mi][j][1]), BV);
                    u64 H23 = add2_(pk2(hacc[mi][j][2], hacc[mi][j][3]), BV);
                    oacc2[mi][j][0] = fma2_(G0, gelu2(H01), oacc2[mi][j][0]);
                    oacc2[mi][j][1] = fma2_(G1, gelu2(H23), oacc2[mi][j][1]);
                }
            }
        }

        // ---- store ----
        #pragma unroll
        for (int mi = 0; mi < 2; mi++) {
            int row = token0 + wm * 32 + mi * 16 + (lane >> 2);
            #pragma unroll
            for (int j = 0; j < 4; j++) {
                int n = col0 + wn * 32 + j * 8 + (lane & 3) * 2;
                float2 v0 = upk2(oacc2[mi][j][0]);
                float2 v1 = upk2(oacc2[mi][j][1]);
                *reinterpret_cast<float2*>(out + (size_t)row * OO + n) = v0;
                *reinterpret_cast<float2*>(out + (size_t)(row + 8) * OO + n) = v1;
            }
        }
    }
}

// ---------------------------------------------------------------------------
// kernel_launch — graph-capturable, allocation-free.
// Inputs: x[4,4096,256] f32, We[16,256,256] f32, be[16,256] f32,
//         Wg[256,16] f32, bg[16] f32. Output: [4,4096,256] f32.
// ---------------------------------------------------------------------------
extern "C" void kernel_launch(void* const* d_in, const int* in_sizes, int n_in,
                              void* d_out, int out_size) {
    const float* x  = (const float*)d_in[0];
    const float* We = (const float*)d_in[1];
    const float* be = (const float*)d_in[2];
    const float* Wg = (const float*)d_in[3];
    const float* bg = (const float*)d_in[4];
    float* out = (float*)d_out;

    cudaFuncSetAttribute(moe_kernel,
                         cudaFuncAttributeMaxDynamicSharedMemorySize, SMEM_TOTAL);

    permute_we<<<512, 256>>>(We);
    moe_kernel<<<(NTOK / TILE_M) * 2, NTHREADS, SMEM_TOTAL>>>(x, be, Wg, bg, out);
}

// round 17
// speedup vs baseline: 1.0349x; 1.0349x over previous
#include <cuda_runtime.h>
#include <cuda_fp16.h>
#include <cstdint>

// ---------------------------------------------------------------------------
// MoE, sm_103: fp16 mma.sync (m16n8k16, fp32 accum) + warp specialization.
//   out[t,o] = sum_e softmax_e(x@Wg+bg)_e * gelu(x@We[e] + be[e])
// B*T=16384, D=256, O=256, E=16.
//
// moe_kernel: CTA = 128 tokens x 128 cols (1 CTA/SM), all 16 experts.
//   18 warps: 16 compute (4Mx4N, warp tile 32x32), 2 producer.
//   Ring = 2 x 64KB (one full expert each), one mbarrier wait per expert.
//   Fully-unrolled wait-free inner loop. Gate + bias staged in smem.
//   Scalar branchless A&S-erf GELU epilogue (R11-proven).
// ---------------------------------------------------------------------------

#define NTOK   16384
#define DD     256
#define OO     256
#define EE     16
#define TILE_M 128
#define TILE_N 128
#define NTHREADS 576          // 16 compute warps + 2 producer warps
#define NBUF   2              // expert-granular double buffer

// smem layout (bytes)
#define SM_A      0                      // fp16 A: [wm4][kc8][ks2][mi2][lane32][16B]
#define SM_A_SIZE 65536
#define SM_B      65536                  // 2 x 64KB expert buffers
#define SM_B_BUF  65536
#define SM_BAR    (SM_B + NBUF * SM_B_BUF)   // 196608
#define MB_FULL(i)  (SM_BAR + (i) * 8)
#define MB_EMPTY(i) (SM_BAR + 16 + (i) * 8)
#define SM_GATE   (SM_BAR + 64)          // 128 rows x 20 floats = 10240 B
#define SM_BE     (SM_GATE + 10240)      // 16 x 128 floats = 8192 B
#define SMEM_TOTAL (SM_BE + 8192)        // 215104 B -> 1 CTA/SM

// scratch: We as fp16 in m16n8k16 fragment order.
__device__ uint4 g_WeBh[EE * DD * OO / 8];   // 2 MB

// ---------------------------------------------------------------------------
__device__ __forceinline__ uint32_t pack_h2(float lo, float hi) {
    __half2 h = __floats2half2_rn(lo, hi);
    return *reinterpret_cast<uint32_t*>(&h);
}
__device__ __forceinline__ uint32_t smem_u32(const void* p) {
    uint32_t a;
    asm("{ .reg .u64 t; cvta.to.shared.u64 t, %1; cvt.u32.u64 %0, t; }"
        : "=r"(a) : "l"(p));
    return a;
}
__device__ __forceinline__ void mma_f16(float* c, const uint4& a,
                                        uint32_t b0, uint32_t b1) {
    asm volatile(
        "mma.sync.aligned.m16n8k16.row.col.f32.f16.f16.f32 "
        "{%0,%1,%2,%3}, {%4,%5,%6,%7}, {%8,%9}, {%0,%1,%2,%3};\n"
        : "+f"(c[0]), "+f"(c[1]), "+f"(c[2]), "+f"(c[3])
        : "r"(a.x), "r"(a.y), "r"(a.z), "r"(a.w), "r"(b0), "r"(b1));
}
__device__ __forceinline__ void cp_async16(uint32_t saddr, const void* gaddr) {
    asm volatile("cp.async.cg.shared.global [%0], [%1], 16;\n"
                 :: "r"(saddr), "l"(gaddr));
}

// Branchless GELU: 0.5*v*(1+erf(v/sqrt2)), erf via A&S 7.1.26 (|err|<=1.5e-7).
__device__ __forceinline__ float gelu_fast(float v) {
    float z = fabsf(v) * 0.70710678118654752f;
    float t = __fdividef(1.0f, fmaf(0.3275911f, z, 1.0f));
    float p = fmaf(t, 1.061405429f, -1.453152027f);
    p = fmaf(t, p, 1.421413741f);
    p = fmaf(t, p, -0.284496736f);
    p = fmaf(t, p, 0.254829592f);
    p = p * t;
    float e  = __expf(-z * z);
    float er = fmaf(-p, e, 1.0f);           // erf(z), z>=0
    er = copysignf(er, v);
    float hv = 0.5f * v;
    return fmaf(hv, er, hv);
}

#define MBAR_INIT(a, n) \
    asm volatile("mbarrier.init.shared.b64 [%0], %1;" :: "r"(a), "r"((uint32_t)(n)) : "memory")
#define MBAR_ARRIVE(a) \
    asm volatile("mbarrier.arrive.shared.b64 _, [%0];" :: "r"(a) : "memory")
#define MBAR_WAIT(a, ph) do {                                                 \
    asm volatile("{\n\t.reg .pred P1;\n\t"                                    \
        "WL_%=:\n\tmbarrier.try_wait.parity.acquire.cta.shared::cta.b64 P1, [%0], %1, 0x989680;\n\t" \
        "@P1 bra.uni WD_%=;\n\tbra.uni WL_%=;\n\tWD_%=:\n\t}"                 \
        :: "r"(a), "r"((uint32_t)(ph)) : "memory");                           \
} while (0)
#define CP_ARRIVE_NOINC(a) \
    asm volatile("cp.async.mbarrier.arrive.noinc.shared::cta.b64 [%0];" :: "r"(a) : "memory")
#define NAMED_BAR(id, n) \
    asm volatile("bar.sync %0, %1;" :: "r"(id), "r"(n) : "memory")

// ---------------------------------------------------------------------------
// Pre-pass: We[e][d][o] -> fp16 m16n8k16 fragment order (unchanged).
// ---------------------------------------------------------------------------
__global__ void permute_we(const float* __restrict__ We) {
    int idx = blockIdx.x * blockDim.x + threadIdx.x;   // 0 .. 131071
    int lane = idx & 31;
    int jp   = (idx >> 5) & 1;
    int ks   = (idx >> 6) & 1;
    int wn   = (idx >> 7) & 3;
    int kc   = (idx >> 9) & 7;
    int ct   = (idx >> 12) & 1;
    int e    = idx >> 13;
    int g = lane >> 2, t = lane & 3;
    int k0 = kc * 32 + ks * 16 + 2 * t;
    int nA = ct * 128 + wn * 32 + jp * 16 + g;
    const float* w = We + (size_t)e * DD * OO;
    uint4 v;
    v.x = pack_h2(w[(size_t)k0 * OO + nA],       w[(size_t)(k0 + 1) * OO + nA]);
    v.y = pack_h2(w[(size_t)(k0 + 8) * OO + nA], w[(size_t)(k0 + 9) * OO + nA]);
    v.z = pack_h2(w[(size_t)k0 * OO + nA + 8],       w[(size_t)(k0 + 1) * OO + nA + 8]);
    v.w = pack_h2(w[(size_t)(k0 + 8) * OO + nA + 8], w[(size_t)(k0 + 9) * OO + nA + 8]);
    g_WeBh[idx] = v;
}

// ---------------------------------------------------------------------------
// Main kernel: 1 CTA/SM, 128x128 tile.
// ---------------------------------------------------------------------------
__global__ __launch_bounds__(NTHREADS, 1)
void moe_kernel(const float* __restrict__ x, const float* __restrict__ be,
                const float* __restrict__ Wg, const float* __restrict__ bg,
                float* __restrict__ out) {
    extern __shared__ float smf[];
    char* smc = reinterpret_cast<char*>(smf);
    const uint32_t sbase = smem_u32(smc);
    const int tid  = threadIdx.x;
    const int wid  = tid >> 5;
    const int lane = tid & 31;
    const int token0 = (blockIdx.x >> 1) * TILE_M;
    const int ct     = blockIdx.x & 1;
    const int col0   = ct * TILE_N;

    if (tid == 0) {
        #pragma unroll
        for (int i = 0; i < NBUF; i++) {
            MBAR_INIT(sbase + MB_FULL(i), 64);   // 64 producer threads, noinc
            MBAR_INIT(sbase + MB_EMPTY(i), 16);  // one arrive per compute warp
        }
    }
    __syncthreads();

    if (wid >= 16) {
        // ========== producer warps: one full expert (64KB) per commit ======
        const int ltid = tid - 512;              // 0..63
        int ph_e[NBUF] = {0, 0};
        #pragma unroll 1
        for (int e = 0; e < EE; e++) {
            const int buf = e & 1;
            if (e >= NBUF) {
                MBAR_WAIT(sbase + MB_EMPTY(buf), ph_e[buf]);
                ph_e[buf] ^= 1;
            }
            const char* gsrc = reinterpret_cast<const char*>(g_WeBh)
                             + (size_t)(e * 2 + ct) * 65536 + ltid * 16;
            const uint32_t dst = sbase + SM_B + (uint32_t)buf * SM_B_BUF
                               + (uint32_t)ltid * 16;
            #pragma unroll
            for (int i = 0; i < 64; i++)
                cp_async16(dst + i * 1024, gsrc + i * 1024);
            CP_ARRIVE_NOINC(sbase + MB_FULL(buf));
        }
    } else {
        // ================= compute warps (16 x 32 threads) =================
        const int wm = wid & 3;          // 4 row groups of 32 tokens
        const int wn = wid >> 2;         // 4 col groups of 32 cols

        // ---- build A (fp16 fragment order): 4096 16B slots --------------
        {
            #pragma unroll
            for (int it = 0; it < 8; it++) {
                int idx = tid + (it << 9);         // tid 0..511
                int ln = idx & 31;
                int mi = (idx >> 5) & 1;
                int ks = (idx >> 6) & 1;
                int kc = (idx >> 7) & 7;
                int wmm = idx >> 10;               // 0..3
                int g = ln >> 2, t = ln & 3;
                int r0 = token0 + wmm * 32 + mi * 16 + g;
                int c0 = kc * 32 + ks * 16 + 2 * t;
                const float* xp = x + (size_t)r0 * DD + c0;
                float2 p00 = *reinterpret_cast<const float2*>(xp);
                float2 p10 = *reinterpret_cast<const float2*>(xp + 8 * DD);
                float2 p01 = *reinterpret_cast<const float2*>(xp + 8);
                float2 p11 = *reinterpret_cast<const float2*>(xp + 8 * DD + 8);
                uint4 v;
                v.x = pack_h2(p00.x, p00.y);
                v.y = pack_h2(p10.x, p10.y);
                v.z = pack_h2(p01.x, p01.y);
                v.w = pack_h2(p11.x, p11.y);
                *reinterpret_cast<uint4*>(smc + SM_A + (size_t)idx * 16) = v;
            }
        }
        // ---- bias slice be[e][col0..col0+128) -> smem -------------------
        {
            int idx = tid;                          // 512 float4 slots
            int e = idx >> 5, f4 = idx & 31;
            float4 v = *reinterpret_cast<const float4*>(
                be + (size_t)e * OO + col0 + f4 * 4);
            *reinterpret_cast<float4*>(smc + SM_BE + (size_t)idx * 16) = v;
        }
        // ---- gate: softmax(x@Wg+bg) -> smem (stride-20 rows) ------------
        {
            const int tok = tid >> 2;          // 0..127
            const int q   = tid & 3;
            float acc0 = 0.f, acc1 = 0.f, acc2 = 0.f, acc3 = 0.f;
            const float4* x4 = reinterpret_cast<const float4*>(
                x + (size_t)(token0 + tok) * DD);
            const float4* wg4 = reinterpret_cast<const float4*>(Wg);
            #pragma unroll 4
            for (int d4 = 0; d4 < 64; d4++) {
                float4 xv = x4[d4];
                float4 w0 = wg4[(d4 * 4 + 0) * 4 + q];
                float4 w1 = wg4[(d4 * 4 + 1) * 4 + q];
                float4 w2 = wg4[(d4 * 4 + 2) * 4 + q];
                float4 w3 = wg4[(d4 * 4 + 3) * 4 + q];
                acc0 += xv.x * w0.x + xv.y * w1.x + xv.z * w2.x + xv.w * w3.x;
                acc1 += xv.x * w0.y + xv.y * w1.y + xv.z * w2.y + xv.w * w3.y;
                acc2 += xv.x * w0.z + xv.y * w1.z + xv.z * w2.z + xv.w * w3.z;
                acc3 += xv.x * w0.w + xv.y * w1.w + xv.z * w2.w + xv.w * w3.w;
            }
            acc0 += __ldg(bg + q * 4 + 0);
            acc1 += __ldg(bg + q * 4 + 1);
            acc2 += __ldg(bg + q * 4 + 2);
            acc3 += __ldg(bg + q * 4 + 3);
            float m = fmaxf(fmaxf(acc0, acc1), fmaxf(acc2, acc3));
            m = fmaxf(m, __shfl_xor_sync(0xFFFFFFFFu, m, 1));
            m = fmaxf(m, __shfl_xor_sync(0xFFFFFFFFu, m, 2));
            float v0 = __expf(acc0 - m), v1 = __expf(acc1 - m);
            float v2 = __expf(acc2 - m), v3 = __expf(acc3 - m);
            float s = v0 + v1 + v2 + v3;
            s += __shfl_xor_sync(0xFFFFFFFFu, s, 1);
            s += __shfl_xor_sync(0xFFFFFFFFu, s, 2);
            float inv = 1.0f / s;
            float4 g = make_float4(v0 * inv, v1 * inv, v2 * inv, v3 * inv);
            *reinterpret_cast<float4*>(
                smc + SM_GATE + ((size_t)tok * 20 + q * 4) * 4) = g;
        }
        NAMED_BAR(1, 512);     // compute warps only: A + gate + bias ready

        float oacc[2][4][4];
        #pragma unroll
        for (int mi = 0; mi < 2; mi++)
            #pragma unroll
            for (int j = 0; j < 4; j++)
                #pragma unroll
                for (int q = 0; q < 4; q++) oacc[mi][j][q] = 0.0f;

        const float* gsm  = reinterpret_cast<const float*>(smc + SM_GATE);
        const float* besm = reinterpret_cast<const float*>(smc + SM_BE);
        int ph_f[NBUF] = {0, 0};

        #pragma unroll 1
        for (int e = 0; e < EE; e++) {
            const int buf = e & 1;
            MBAR_WAIT(sbase + MB_FULL(buf), ph_f[buf]);
            ph_f[buf] ^= 1;

            float hacc[2][4][4];
            #pragma unroll
            for (int mi = 0; mi < 2; mi++)
                #pragma unroll
                for (int j = 0; j < 4; j++)
                    #pragma unroll
                    for (int q = 0; q < 4; q++) hacc[mi][j][q] = 0.0f;

            const char* bbuf = smc + SM_B + buf * SM_B_BUF;
            const char* abase = smc + SM_A + wm * 16384 + lane * 16;

            // wait-free inner loop: fully unrolled 8 chunks of LDS+MMA
            #pragma unroll
            for (int kc = 0; kc < 8; kc++) {
                const char* ab = abase + kc * 2048;
                const char* bp0 = bbuf + kc * 8192 + wn * 2048 + lane * 16;
                #pragma unroll
                for (int ks = 0; ks < 2; ks++) {
                    uint4 A0 = *reinterpret_cast<const uint4*>(ab + ks * 1024);
                    uint4 A1 = *reinterpret_cast<const uint4*>(ab + ks * 1024 + 512);
                    const char* bp = bp0 + ks * 1024;
                    uint4 B0 = *reinterpret_cast<const uint4*>(bp);
                    uint4 B1 = *reinterpret_cast<const uint4*>(bp + 512);
                    mma_f16(hacc[0][0], A0, B0.x, B0.y);
                    mma_f16(hacc[1][0], A1, B0.x, B0.y);
                    mma_f16(hacc[0][1], A0, B0.z, B0.w);
                    mma_f16(hacc[1][1], A1, B0.z, B0.w);
                    mma_f16(hacc[0][2], A0, B1.x, B1.y);
                    mma_f16(hacc[1][2], A1, B1.x, B1.y);
                    mma_f16(hacc[0][3], A0, B1.z, B1.w);
                    mma_f16(hacc[1][3], A1, B1.z, B1.w);
                }
            }
            if (lane == 0) MBAR_ARRIVE(sbase + MB_EMPTY(buf));

            // epilogue: bias + branchless gelu + gate-weighted accumulate
            #pragma unroll
            for (int mi = 0; mi < 2; mi++) {
                int rl = wm * 32 + mi * 16 + (lane >> 2);    // local row
                float g0 = gsm[rl * 20 + e];
                float g1 = gsm[(rl + 8) * 20 + e];
                #pragma unroll
                for (int j = 0; j < 4; j++) {
                    int n0 = wn * 32 + j * 8 + (lane & 3) * 2;   // local col
                    float2 bv = *reinterpret_cast<const float2*>(
                        besm + e * 128 + n0);
                    oacc[mi][j][0] = fmaf(g0, gelu_fast(hacc[mi][j][0] + bv.x), oacc[mi][j][0]);
                    oacc[mi][j][1] = fmaf(g0, gelu_fast(hacc[mi][j][1] + bv.y), oacc[mi][j][1]);
                    oacc[mi][j][2] = fmaf(g1, gelu_fast(hacc[mi][j][2] + bv.x), oacc[mi][j][2]);
                    oacc[mi][j][3] = fmaf(g1, gelu_fast(hacc[mi][j][3] + bv.y), oacc[mi][j][3]);
                }
            }
        }

        // ---- store ----
        #pragma unroll
        for (int mi = 0; mi < 2; mi++) {
            int row = token0 + wm * 32 + mi * 16 + (lane >> 2);
            #pragma unroll
            for (int j = 0; j < 4; j++) {
                int n = col0 + wn * 32 + j * 8 + (lane & 3) * 2;
                float2 v0 = make_float2(oacc[mi][j][0], oacc[mi][j][1]);
                float2 v1 = make_float2(oacc[mi][j][2], oacc[mi][j][3]);
                *reinterpret_cast<float2*>(out + (size_t)row * OO + n) = v0;
                *reinterpret_cast<float2*>(out + (size_t)(row + 8) * OO + n) = v1;
            }
        }
    }
}

// ---------------------------------------------------------------------------
// kernel_launch — graph-capturable, allocation-free.
// Inputs: x[4,4096,256] f32, We[16,256,256] f32, be[16,256] f32,
//         Wg[256,16] f32, bg[16] f32. Output: [4,4096,256] f32.
// ---------------------------------------------------------------------------
extern "C" void kernel_launch(void* const* d_in, const int* in_sizes, int n_in,
                              void* d_out, int out_size) {
    const float* x  = (const float*)d_in[0];
    const float* We = (const float*)d_in[1];
    const float* be = (const float*)d_in[2];
    const float* Wg = (const float*)d_in[3];
    const float* bg = (const float*)d_in[4];
    float* out = (float*)d_out;

    cudaFuncSetAttribute(moe_kernel,
                         cudaFuncAttributeMaxDynamicSharedMemorySize, SMEM_TOTAL);

    permute_we<<<512, 256>>>(We);
    moe_kernel<<<(NTOK / TILE_M) * 2, NTHREADS, SMEM_TOTAL>>>(x, be, Wg, bg, out);
}